// round 2
// baseline (speedup 1.0000x reference)
#include <cuda_runtime.h>

// GraphMultiHeadAttention: B=8, N=1024, D=256, H=4, HO=64, T=5
// K1: h[b,h,n,e] = x[b,n,:] @ W[h,:,e]
// K1b: e_src/e_dst[b,h,t,n] = h[b,h,n,:] . a_{src,dst}[h,t,:]
// K2: masked edge-typed attention + AV + bias/relu/residual/LayerNorm + head concat

#define BB 8
#define NN 1024
#define DD 256
#define HH 4
#define HOO 64
#define TT 5
#define RR 32     // rows per CTA in K2
#define JC 32     // j-chunk in K2
#define NT 16     // nodes per CTA in K1

__device__ float g_h[BB * HH * NN * HOO];      // [B,H,N,HO]
__device__ float g_es[BB * HH * TT * NN];      // [B,H,T,N]
__device__ float g_ed[BB * HH * TT * NN];      // [B,H,T,N]

// ---------------------------------------------------------------------------
// K1: projection. Grid: B*N/NT = 512 blocks, 256 threads.
// Thread owns (h,ho) column for NT nodes; x tile staged in smem [d][node].
// ---------------------------------------------------------------------------
__global__ __launch_bounds__(256) void k_project(const float* __restrict__ x,
                                                 const float* __restrict__ W) {
    __shared__ float xs[DD][NT];
    const int blk = blockIdx.x;
    const int b = blk >> 6;              // N/NT = 64 tiles per batch
    const int n0 = (blk & 63) * NT;
    const int tid = threadIdx.x;

    // load x tile: thread = d, loop nodes (coalesced over d per node)
    {
        const float* xp = x + ((b * NN + n0) * DD) + tid;
#pragma unroll
        for (int nt = 0; nt < NT; nt++) xs[tid][nt] = xp[nt * DD];
    }
    __syncthreads();

    const int h = tid >> 6, ho = tid & 63;
    float acc[NT];
#pragma unroll
    for (int i = 0; i < NT; i++) acc[i] = 0.f;

    const float* wp = W + (h * DD) * HOO + ho;
#pragma unroll 4
    for (int d = 0; d < DD; d++) {
        const float w = wp[d * HOO];
        const float4* x4 = reinterpret_cast<const float4*>(&xs[d][0]);
#pragma unroll
        for (int g = 0; g < NT / 4; g++) {
            const float4 v = x4[g];
            acc[g * 4 + 0] += v.x * w;
            acc[g * 4 + 1] += v.y * w;
            acc[g * 4 + 2] += v.z * w;
            acc[g * 4 + 3] += v.w * w;
        }
    }

    float* hp = g_h + ((b * HH + h) * NN + n0) * HOO + ho;
#pragma unroll
    for (int nt = 0; nt < NT; nt++) hp[nt * HOO] = acc[nt];
}

// ---------------------------------------------------------------------------
// K1b: score tables. Grid: 1024 blocks x 256 threads; warp = one node.
// ---------------------------------------------------------------------------
__global__ __launch_bounds__(256) void k_scores(const float* __restrict__ a_src,
                                                const float* __restrict__ a_dst) {
    const int warp = threadIdx.x >> 5, lane = threadIdx.x & 31;
    const int node = blockIdx.x * 8 + warp;      // 0..8191
    const int b = node >> 10;
    const int n = node & (NN - 1);

    float hv[2 * HH];
#pragma unroll
    for (int h = 0; h < HH; h++) {
        const float* hp = g_h + ((b * HH + h) * NN + n) * HOO;
        hv[h * 2 + 0] = hp[lane];
        hv[h * 2 + 1] = hp[32 + lane];
    }

#pragma unroll
    for (int h = 0; h < HH; h++) {
#pragma unroll
        for (int t = 0; t < TT; t++) {
            const int wi = (h * TT + t) * HOO;
            float ps = hv[h * 2] * a_src[wi + lane] + hv[h * 2 + 1] * a_src[wi + 32 + lane];
            float pd = hv[h * 2] * a_dst[wi + lane] + hv[h * 2 + 1] * a_dst[wi + 32 + lane];
#pragma unroll
            for (int off = 16; off; off >>= 1) {
                ps += __shfl_xor_sync(0xffffffffu, ps, off);
                pd += __shfl_xor_sync(0xffffffffu, pd, off);
            }
            if (lane == 0) {
                g_es[(b * HH + h) * TT * NN + t * NN + n] = ps;
                g_ed[(b * HH + h) * TT * NN + t * NN + n] = pd;
            }
        }
    }
}

// ---------------------------------------------------------------------------
// K2: attention + epilogue. Grid: (N/RR=32, B=8), 256 threads.
//   phase A (warp = 4 rows, lane = j): p = exp(lrelu(es+ed)) or 0; sums in regs
//   phase B (thread = (h,ho)): acc[r] += p * h[j]  via float4 LDS over j
//   epilogue: /sum + bias -> relu -> +h -> LayerNorm -> concat-head store
// ---------------------------------------------------------------------------
__global__ __launch_bounds__(256) void k_attn(const int* __restrict__ adj,
                                              const float* __restrict__ bias,
                                              const float* __restrict__ gamma,
                                              const float* __restrict__ beta,
                                              float* __restrict__ out) {
    __shared__ float es_s[RR][HH][TT];
    __shared__ float p_s[HH][RR][JC];       // [h][row][j] -> float4 over j
    __shared__ float sum_s[RR][HH];
    __shared__ float2 red_s[RR][8];

    const int b = blockIdx.y;
    const int i0 = blockIdx.x * RR;
    const int tid = threadIdx.x;
    const int w = tid >> 5, lane = tid & 31;
    const int h = tid >> 6, ho = tid & 63;

    // load e_src for our rows into smem
    for (int idx = tid; idx < RR * HH * TT; idx += 256) {
        const int r = idx / (HH * TT);
        const int rem = idx % (HH * TT);
        const int hh2 = rem / TT, t = rem % TT;
        es_s[r][hh2][t] = g_es[(b * HH + hh2) * TT * NN + t * NN + i0 + r];
    }

    float acc[RR];
#pragma unroll
    for (int r = 0; r < RR; r++) acc[r] = 0.f;

    float psum[4][HH];
#pragma unroll
    for (int rl = 0; rl < 4; rl++)
#pragma unroll
        for (int hh2 = 0; hh2 < HH; hh2++) psum[rl][hh2] = 0.f;

    __syncthreads();

    const int* adjp = adj + b * NN * NN;
    const float* edb = g_ed + (b * HH) * TT * NN;
    const float* hb = g_h + ((b * HH + h) * NN) * HOO + ho;

    for (int c = 0; c < NN / JC; c++) {
        const int j0 = c * JC;
        // ---- phase A: scores -> p ----
#pragma unroll
        for (int rl = 0; rl < 4; rl++) {
            const int r = w * 4 + rl;
            const int t = adjp[(i0 + r) * NN + j0 + lane];
#pragma unroll
            for (int hh2 = 0; hh2 < HH; hh2++) {
                float p = 0.f;
                if (t > 0) {
                    float s = es_s[r][hh2][t - 1] +
                              __ldg(&edb[(hh2 * TT + (t - 1)) * NN + j0 + lane]);
                    s = s > 0.f ? s : 0.01f * s;
                    p = __expf(s);
                }
                psum[rl][hh2] += p;
                p_s[hh2][r][lane] = p;
            }
        }
        __syncthreads();
        // ---- phase B: acc += p * h ----
#pragma unroll 2
        for (int jg = 0; jg < JC / 4; jg++) {
            const int j = j0 + jg * 4;
            const float v0 = hb[(j + 0) * HOO];
            const float v1 = hb[(j + 1) * HOO];
            const float v2 = hb[(j + 2) * HOO];
            const float v3 = hb[(j + 3) * HOO];
            const float4* pp = reinterpret_cast<const float4*>(&p_s[h][0][jg * 4]);
#pragma unroll
            for (int r = 0; r < RR; r++) {
                const float4 pv = pp[r * (JC / 4)];
                acc[r] += pv.x * v0 + pv.y * v1 + pv.z * v2 + pv.w * v3;
            }
        }
        __syncthreads();
    }

    // finalize softmax denominators
#pragma unroll
    for (int rl = 0; rl < 4; rl++)
#pragma unroll
        for (int hh2 = 0; hh2 < HH; hh2++) {
            float s = psum[rl][hh2];
#pragma unroll
            for (int off = 16; off; off >>= 1) s += __shfl_xor_sync(0xffffffffu, s, off);
            if (lane == 0) sum_s[w * 4 + rl][hh2] = s;
        }
    __syncthreads();

    // epilogue
    const float bias_v = bias[h * HOO + ho];
    const float gam = gamma[h * HOO + ho];
    const float bet = beta[h * HOO + ho];

#pragma unroll 4
    for (int r = 0; r < RR; r++) {
        const float hres = hb[(i0 + r) * HOO];
        float v = __fdividef(acc[r], sum_s[r][h]) + bias_v;
        v = fmaxf(v, 0.f) + hres;
        acc[r] = v;
        float s = v, s2 = v * v;
#pragma unroll
        for (int off = 16; off; off >>= 1) {
            s += __shfl_xor_sync(0xffffffffu, s, off);
            s2 += __shfl_xor_sync(0xffffffffu, s2, off);
        }
        if (lane == 0) red_s[r][w] = make_float2(s, s2);
    }
    __syncthreads();

#pragma unroll 4
    for (int r = 0; r < RR; r++) {
        const float2 a0 = red_s[r][h * 2 + 0];
        const float2 a1 = red_s[r][h * 2 + 1];
        const float mu = (a0.x + a1.x) * (1.f / HOO);
        const float var = (a0.y + a1.y) * (1.f / HOO) - mu * mu;
        const float o = (acc[r] - mu) * rsqrtf(var + 1e-6f) * gam + bet;
        out[(b * NN + i0 + r) * (HH * HOO) + h * HOO + ho] = o;
    }
}

// ---------------------------------------------------------------------------
extern "C" void kernel_launch(void* const* d_in, const int* in_sizes, int n_in,
                              void* d_out, int out_size) {
    const float* nodes_embed = (const float*)d_in[0];
    const int*   node_adj    = (const int*)d_in[1];
    const float* W           = (const float*)d_in[2];
    const float* a_src       = (const float*)d_in[3];
    const float* a_dst       = (const float*)d_in[4];
    const float* bias        = (const float*)d_in[5];
    const float* ln_gamma    = (const float*)d_in[6];
    const float* ln_beta     = (const float*)d_in[7];
    float* out = (float*)d_out;

    k_project<<<BB * NN / NT, 256>>>(nodes_embed, W);
    k_scores<<<BB * NN / 8, 256>>>(a_src, a_dst);
    k_attn<<<dim3(NN / RR, BB), 256>>>(node_adj, bias, ln_gamma, ln_beta, out);
}

// round 5
// speedup vs baseline: 1.6510x; 1.6510x over previous
#include <cuda_runtime.h>

// GraphMultiHeadAttention: B=8, N=1024, D=256, H=4, HO=64, T=5
// K1: h = x @ W (per head), f32x2 packed FMA
// K1b: e_src/e_dst score tables
// K2: masked edge-typed attention + AV (f32x2) + bias/relu/residual/LN + concat

#define BB 8
#define NN 1024
#define DD 256
#define HH 4
#define HOO 64
#define TT 5
#define RR 32     // rows per CTA in K2
#define JC 32     // j-chunk in K2
#define NCH (NN / JC)

typedef unsigned long long u64;

__device__ float g_h[BB * HH * NN * HOO];      // [B,H,N,HO]
__device__ float g_es[BB * HH * TT * NN];      // [B,H,T,N]
__device__ float g_ed[BB * HH * TT * NN];      // [B,H,T,N]

__device__ __forceinline__ u64 pack2(float lo, float hi) {
    u64 r; asm("mov.b64 %0, {%1, %2};" : "=l"(r) : "f"(lo), "f"(hi)); return r;
}
__device__ __forceinline__ void fma2(u64& acc, u64 a, u64 b) {
    asm("fma.rn.f32x2 %0, %1, %2, %0;" : "+l"(acc) : "l"(a), "l"(b));
}
__device__ __forceinline__ float2 unpack2(u64 v) {
    float2 f; asm("mov.b64 {%0, %1}, %2;" : "=f"(f.x), "=f"(f.y) : "l"(v)); return f;
}

// ---------------------------------------------------------------------------
// K1: projection. Grid: B*N/32 = 256 blocks, 256 threads.
// 32 nodes per CTA; thread owns (h,ho); f32x2 over node pairs.
// smem padded to 34 floats/row: conflict-reduced STS, 8B-aligned b64 LDS.
// ---------------------------------------------------------------------------
__global__ __launch_bounds__(256) void k_project(const float* __restrict__ x,
                                                 const float* __restrict__ W) {
    __shared__ float xs[DD][34];
    const int b = blockIdx.x >> 5;
    const int n0 = (blockIdx.x & 31) * 32;
    const int tid = threadIdx.x;

    {
        const float* xp = x + (b * NN + n0) * DD + tid;
#pragma unroll
        for (int nt = 0; nt < 32; nt++) xs[tid][nt] = xp[nt * DD];
    }
    __syncthreads();

    const int h = tid >> 6, ho = tid & 63;
    u64 acc2[16];
#pragma unroll
    for (int i = 0; i < 16; i++) acc2[i] = 0ull;

    const float* wp = W + h * DD * HOO + ho;
#pragma unroll 4
    for (int d = 0; d < DD; d++) {
        const float w = __ldg(wp + d * HOO);
        const u64 ww = pack2(w, w);
#pragma unroll
        for (int i = 0; i < 16; i++) {
            const u64 xv = *reinterpret_cast<const u64*>(&xs[d][i * 2]);
            fma2(acc2[i], xv, ww);
        }
    }

    float* hp = g_h + ((b * HH + h) * NN + n0) * HOO + ho;
#pragma unroll
    for (int i = 0; i < 16; i++) {
        const float2 f = unpack2(acc2[i]);
        hp[(2 * i + 0) * HOO] = f.x;
        hp[(2 * i + 1) * HOO] = f.y;
    }
}

// ---------------------------------------------------------------------------
// K1b: score tables. Grid: 1024 blocks x 256 threads; warp = one node.
// ---------------------------------------------------------------------------
__global__ __launch_bounds__(256) void k_scores(const float* __restrict__ a_src,
                                                const float* __restrict__ a_dst) {
    const int warp = threadIdx.x >> 5, lane = threadIdx.x & 31;
    const int node = blockIdx.x * 8 + warp;
    const int b = node >> 10;
    const int n = node & (NN - 1);

    float hv[2 * HH];
#pragma unroll
    for (int h = 0; h < HH; h++) {
        const float* hp = g_h + ((b * HH + h) * NN + n) * HOO;
        hv[h * 2 + 0] = hp[lane];
        hv[h * 2 + 1] = hp[32 + lane];
    }

#pragma unroll
    for (int h = 0; h < HH; h++) {
#pragma unroll
        for (int t = 0; t < TT; t++) {
            const int wi = (h * TT + t) * HOO;
            float ps = hv[h * 2] * a_src[wi + lane] + hv[h * 2 + 1] * a_src[wi + 32 + lane];
            float pd = hv[h * 2] * a_dst[wi + lane] + hv[h * 2 + 1] * a_dst[wi + 32 + lane];
#pragma unroll
            for (int off = 16; off; off >>= 1) {
                ps += __shfl_xor_sync(0xffffffffu, ps, off);
                pd += __shfl_xor_sync(0xffffffffu, pd, off);
            }
            if (lane == 0) {
                g_es[(b * HH + h) * TT * NN + t * NN + n] = ps;
                g_ed[(b * HH + h) * TT * NN + t * NN + n] = pd;
            }
        }
    }
}

// ---------------------------------------------------------------------------
// K2: attention + epilogue. Grid: (N/RR=32, B=8), 512 threads, 16 warps.
// Software-pipelined: one __syncthreads per j-chunk; p_s and ed_s double-buffered.
//   phase A (warp = 2 rows, lane = j): p = exp(lrelu(es+ed)) masked; psum in regs
//   phase B (thread = (rhalf,h,ho)): acc2[16 rows] += p * v  via f32x2
// ---------------------------------------------------------------------------
__global__ __launch_bounds__(512) void k_attn(const int* __restrict__ adj,
                                              const float* __restrict__ bias,
                                              const float* __restrict__ gamma,
                                              const float* __restrict__ beta,
                                              float* __restrict__ out) {
    __shared__ float es_s[RR][HH][TT];            // 2.5 KB
    __shared__ float ed_s[2][HH * TT * JC];       // 5 KB (flat per buffer)
    __shared__ float p_s[2][HH][RR][JC];          // 32 KB
    __shared__ float sum_s[RR][HH];
    __shared__ float2 red_s[RR][HH][2];

    const int b = blockIdx.y;
    const int i0 = blockIdx.x * RR;
    const int tid = threadIdx.x;
    const int w = tid >> 5, lane = tid & 31;
    // phase B / epilogue roles
    const int rh = tid >> 8;                 // 0..1 -> rows [rh*16, rh*16+16)
    const int h = (tid >> 6) & 3;
    const int ho = tid & 63;
    const int r0 = rh * 16;
    const int half = (tid >> 5) & 1;

    // e_src tile for our 32 rows
    for (int idx = tid; idx < RR * HH * TT; idx += 512) {
        const int r = idx / (HH * TT);
        const int rem = idx % (HH * TT);
        es_s[r][rem / TT][rem % TT] =
            g_es[(b * HH + rem / TT) * TT * NN + (rem % TT) * NN + i0 + r];
    }

    u64 acc2[16];
#pragma unroll
    for (int i = 0; i < 16; i++) acc2[i] = 0ull;
    float psum[2][HH];
#pragma unroll
    for (int rl = 0; rl < 2; rl++)
#pragma unroll
        for (int hh = 0; hh < HH; hh++) psum[rl][hh] = 0.f;

    const int* adjp = adj + b * NN * NN + i0 * NN;
    const float* edb = g_ed + b * HH * TT * NN;
    const float* hb = g_h + ((b * HH + h) * NN) * HOO + ho;

    // ed-chunk staging map: idx -> (hh, t, j); global off = (hh*TT+t)*NN + j0 + j
    const int s_hh = tid / (TT * JC);
    const int s_t = (tid % (TT * JC)) / JC;
    const int s_j = tid & (JC - 1);
    const int s_off = (s_hh * TT + s_t) * NN + s_j;        // + j0
    const int tid2 = tid + 512;                            // 512..639 (tid<128)
    const int s2_hh = tid2 / (TT * JC);
    const int s2_t = (tid2 % (TT * JC)) / JC;
    const int s2_j = tid2 & (JC - 1);
    const int s2_off = (s2_hh * TT + s2_t) * NN + s2_j;

#define STAGE_ED_LOAD(j0next)                                   \
    do {                                                        \
        e0 = __ldg(&edb[s_off + (j0next)]);                     \
        if (tid < 128) e1 = __ldg(&edb[s2_off + (j0next)]);     \
    } while (0)

#define STAGE_ED_STORE(nb)                                      \
    do {                                                        \
        ed_s[nb][tid] = e0;                                     \
        if (tid < 128) ed_s[nb][tid2] = e1;                     \
    } while (0)

#define PHASE_A(cbuf, jj0)                                                     \
    do {                                                                       \
        const float* edc = ed_s[cbuf];                                         \
        _Pragma("unroll")                                                      \
        for (int rl = 0; rl < 2; rl++) {                                       \
            const int r = w * 2 + rl;                                          \
            const int t = (rl == 0) ? t0 : t1;                                 \
            _Pragma("unroll")                                                  \
            for (int hh = 0; hh < HH; hh++) {                                  \
                float p = 0.f;                                                 \
                if (t > 0) {                                                   \
                    float s = es_s[r][hh][t - 1] +                             \
                              edc[(hh * TT + (t - 1)) * JC + lane];            \
                    s = s > 0.f ? s : 0.01f * s;                               \
                    p = __expf(s);                                             \
                }                                                              \
                psum[rl][hh] += p;                                             \
                p_s[cbuf][hh][r][lane] = p;                                    \
            }                                                                  \
        }                                                                      \
    } while (0)

#define PHASE_B(jj0, pbuf)                                                     \
    do {                                                                       \
        _Pragma("unroll")                                                      \
        for (int jg = 0; jg < JC / 4; jg++) {                                  \
            const float* vp = hb + ((jj0) + jg * 4) * HOO;                     \
            const float v0 = __ldg(vp);                                        \
            const float v1 = __ldg(vp + HOO);                                  \
            const float v2 = __ldg(vp + 2 * HOO);                              \
            const float v3 = __ldg(vp + 3 * HOO);                              \
            const u64 v01 = pack2(v0, v1);                                     \
            const u64 v23 = pack2(v2, v3);                                     \
            _Pragma("unroll")                                                  \
            for (int ri = 0; ri < 16; ri++) {                                  \
                const float4 pv = *reinterpret_cast<const float4*>(            \
                    &p_s[pbuf][h][r0 + ri][jg * 4]);                           \
                fma2(acc2[ri], pack2(pv.x, pv.y), v01);                        \
                fma2(acc2[ri], pack2(pv.z, pv.w), v23);                        \
            }                                                                  \
        }                                                                      \
    } while (0)

    float e0 = 0.f, e1 = 0.f;
    int t0, t1;

    // ---- pipeline prologue ----
    STAGE_ED_LOAD(0);
    STAGE_ED_STORE(0);
    __syncthreads();
    t0 = adjp[(w * 2 + 0) * NN + lane];
    t1 = adjp[(w * 2 + 1) * NN + lane];
    STAGE_ED_LOAD(JC);                 // chunk 1 loads in flight
    PHASE_A(0, 0);
    STAGE_ED_STORE(1);
    __syncthreads();

    // ---- main pipeline: one sync per chunk ----
    for (int c = 1; c < NCH; c++) {
        const int j0 = c * JC;
        const int cbuf = c & 1;
        t0 = adjp[(w * 2 + 0) * NN + j0 + lane];
        t1 = adjp[(w * 2 + 1) * NN + j0 + lane];
        if (c + 1 < NCH) STAGE_ED_LOAD(j0 + JC);
        PHASE_B(j0 - JC, cbuf ^ 1);
        PHASE_A(cbuf, j0);
        if (c + 1 < NCH) STAGE_ED_STORE(cbuf ^ 1);
        __syncthreads();
    }
    PHASE_B(NN - JC, (NCH - 1) & 1);

    // ---- softmax denominators ----
#pragma unroll
    for (int rl = 0; rl < 2; rl++)
#pragma unroll
        for (int hh = 0; hh < HH; hh++) {
            float s = psum[rl][hh];
#pragma unroll
            for (int off = 16; off; off >>= 1) s += __shfl_xor_sync(0xffffffffu, s, off);
            if (lane == 0) sum_s[w * 2 + rl][hh] = s;
        }
    __syncthreads();

    // ---- epilogue: /sum + bias -> relu -> +h -> LayerNorm -> concat store ----
    const float bias_v = bias[h * HOO + ho];
    const float gam = gamma[h * HOO + ho];
    const float bet = beta[h * HOO + ho];

#pragma unroll
    for (int ri = 0; ri < 16; ri++) {
        const int r = r0 + ri;
        const float2 f = unpack2(acc2[ri]);
        const float hres = hb[(i0 + r) * HOO];
        float v = __fdividef(f.x + f.y, sum_s[r][h]) + bias_v;
        v = fmaxf(v, 0.f) + hres;
        acc2[ri] = pack2(v, v);
        float s = v, s2 = v * v;
#pragma unroll
        for (int off = 16; off; off >>= 1) {
            s += __shfl_xor_sync(0xffffffffu, s, off);
            s2 += __shfl_xor_sync(0xffffffffu, s2, off);
        }
        if (lane == 0) red_s[r][h][half] = make_float2(s, s2);
    }
    __syncthreads();

#pragma unroll
    for (int ri = 0; ri < 16; ri++) {
        const int r = r0 + ri;
        const float2 a0 = red_s[r][h][0];
        const float2 a1 = red_s[r][h][1];
        const float mu = (a0.x + a1.x) * (1.f / HOO);
        const float var = (a0.y + a1.y) * (1.f / HOO) - mu * mu;
        const float o = (unpack2(acc2[ri]).x - mu) * rsqrtf(var + 1e-6f) * gam + bet;
        out[(b * NN + i0 + r) * (HH * HOO) + h * HOO + ho] = o;
    }
#undef STAGE_ED_LOAD
#undef STAGE_ED_STORE
#undef PHASE_A
#undef PHASE_B
}

// ---------------------------------------------------------------------------
extern "C" void kernel_launch(void* const* d_in, const int* in_sizes, int n_in,
                              void* d_out, int out_size) {
    const float* nodes_embed = (const float*)d_in[0];
    const int*   node_adj    = (const int*)d_in[1];
    const float* W           = (const float*)d_in[2];
    const float* a_src       = (const float*)d_in[3];
    const float* a_dst       = (const float*)d_in[4];
    const float* bias        = (const float*)d_in[5];
    const float* ln_gamma    = (const float*)d_in[6];
    const float* ln_beta     = (const float*)d_in[7];
    float* out = (float*)d_out;

    k_project<<<BB * NN / 32, 256>>>(nodes_embed, W);
    k_scores<<<BB * NN / 8, 256>>>(a_src, a_dst);
    k_attn<<<dim3(NN / RR, BB), 512>>>(node_adj, bias, ln_gamma, ln_beta, out);
}